// round 2
// baseline (speedup 1.0000x reference)
#include <cuda_runtime.h>
#include <cstdint>

// SimpleSparseConvNet: rulebook sparse conv, Cin=1, Cout=16.
// Strategy: build CSR (output -> list of (in_idx, k)) on device, then gather.
// No float atomics, no output memset: every output element is written once.

#define MAX_NOUT (4 * 1024 * 1024)
#define MAX_M    (8 * 1024 * 1024)
#define CHUNK    4096
#define MAX_BLKS (MAX_NOUT / CHUNK)   // 1024

__device__ unsigned int g_counts[MAX_NOUT + 1];
__device__ unsigned int g_offsets[MAX_NOUT + 1];
__device__ unsigned int g_cursors[MAX_NOUT];
__device__ unsigned int g_entries[MAX_M];
__device__ unsigned int g_partials[MAX_BLKS];

// ---- K0: zero counts -------------------------------------------------------
__global__ void __launch_bounds__(256)
k_zero_counts(int n) {
    int i = blockIdx.x * blockDim.x + threadIdx.x;
    if (i <= n) g_counts[i] = 0u;
}

// ---- K1: histogram of out_idx ---------------------------------------------
__global__ void __launch_bounds__(256)
k_count(const int* __restrict__ out_idx, int M) {
    int m = blockIdx.x * blockDim.x + threadIdx.x;
    if (m < M) atomicAdd(&g_counts[out_idx[m]], 1u);
}

// ---- K2: per-block exclusive scan over CHUNK counts -> offsets, partials ---
__global__ void __launch_bounds__(256)
k_scan_block(int n) {
    __shared__ unsigned int sh[256];
    const int t = threadIdx.x;
    const int base = blockIdx.x * CHUNK + t * 16;

    unsigned int v[16];
    unsigned int s = 0;
#pragma unroll
    for (int i = 0; i < 16; i++) {
        int idx = base + i;
        unsigned int c = (idx < n) ? g_counts[idx] : 0u;
        v[i] = s;          // exclusive prefix within thread
        s += c;
    }
    sh[t] = s;
    __syncthreads();
    // Hillis-Steele inclusive scan over 256 thread sums
#pragma unroll
    for (int d = 1; d < 256; d <<= 1) {
        unsigned int x = (t >= d) ? sh[t - d] : 0u;
        __syncthreads();
        sh[t] += x;
        __syncthreads();
    }
    unsigned int excl = (t > 0) ? sh[t - 1] : 0u;
#pragma unroll
    for (int i = 0; i < 16; i++) {
        int idx = base + i;
        if (idx < n) g_offsets[idx] = excl + v[i];
    }
    if (t == 255) g_partials[blockIdx.x] = sh[255];
}

// ---- K3: single-block exclusive scan of block partials ---------------------
__global__ void __launch_bounds__(1024)
k_scan_partials(int nb) {
    __shared__ unsigned int sh[1024];
    const int t = threadIdx.x;
    sh[t] = (t < nb) ? g_partials[t] : 0u;
    __syncthreads();
#pragma unroll
    for (int d = 1; d < 1024; d <<= 1) {
        unsigned int x = (t >= d) ? sh[t - d] : 0u;
        __syncthreads();
        sh[t] += x;
        __syncthreads();
    }
    unsigned int excl = (t > 0) ? sh[t - 1] : 0u;
    if (t < nb) g_partials[t] = excl;
}

// ---- K4: add block bases; init cursors; set offsets[n] = M -----------------
__global__ void __launch_bounds__(256)
k_add_base(int n, int M) {
    int i = blockIdx.x * blockDim.x + threadIdx.x;
    if (i < n) {
        unsigned int off = g_offsets[i] + g_partials[i / CHUNK];
        g_offsets[i] = off;
        g_cursors[i] = off;
    }
    if (i == 0) g_offsets[n] = (unsigned int)M;
}

// ---- K5: scatter packed (in_idx | k<<27) entries into CSR slots ------------
__global__ void __launch_bounds__(256)
k_scatter(const int* __restrict__ in_idx, const int* __restrict__ out_idx,
          const int* __restrict__ k_idx, int M) {
    int m = blockIdx.x * blockDim.x + threadIdx.x;
    if (m < M) {
        int o = out_idx[m];
        unsigned int pos = atomicAdd(&g_cursors[o], 1u);
        g_entries[pos] = (unsigned int)in_idx[m] | ((unsigned int)k_idx[m] << 27);
    }
}

// ---- K6: gather. 4 lanes per output, one float4 quad each, STG.128 ---------
__global__ void __launch_bounds__(256)
k_gather(const float* __restrict__ feats, const float* __restrict__ weight,
         float* __restrict__ out, int n_out) {
    int tid = blockIdx.x * blockDim.x + threadIdx.x;
    int o = tid >> 2;
    int j = tid & 3;
    if (o >= n_out) return;

    unsigned int s = g_offsets[o];
    unsigned int e = g_offsets[o + 1];

    float4 acc = make_float4(0.f, 0.f, 0.f, 0.f);
    const float4* w4 = reinterpret_cast<const float4*>(weight);
    for (unsigned int p = s; p < e; p++) {
        unsigned int ent = g_entries[p];           // broadcast across 4 lanes
        unsigned int i = ent & 0x7FFFFFFu;
        unsigned int k = ent >> 27;
        float f = __ldg(&feats[i]);
        float4 w = __ldg(&w4[k * 4 + j]);
        acc.x += f * w.x;
        acc.y += f * w.y;
        acc.z += f * w.z;
        acc.w += f * w.w;
    }
    reinterpret_cast<float4*>(out)[(size_t)o * 4 + j] = acc;   // coalesced
}

extern "C" void kernel_launch(void* const* d_in, const int* in_sizes, int n_in,
                              void* d_out, int out_size) {
    const float* feats  = (const float*)d_in[0];
    const float* weight = (const float*)d_in[1];
    const int* in_idx   = (const int*)d_in[2];
    const int* out_idx  = (const int*)d_in[3];
    const int* k_idx    = (const int*)d_in[4];
    float* out = (float*)d_out;

    const int M = in_sizes[2];
    const int n_out = out_size / 16;
    const int nb = (n_out + CHUNK - 1) / CHUNK;

    const int T = 256;
    k_zero_counts<<<(n_out + 1 + T) / T, T>>>(n_out);
    k_count<<<(M + T - 1) / T, T>>>(out_idx, M);
    k_scan_block<<<nb, T>>>(n_out);
    k_scan_partials<<<1, 1024>>>(nb);
    k_add_base<<<(n_out + T - 1) / T, T>>>(n_out, M);
    k_scatter<<<(M + T - 1) / T, T>>>(in_idx, out_idx, k_idx, M);
    k_gather<<<((n_out * 4) + T - 1) / T, T>>>(feats, weight, out, n_out);
}

// round 3
// speedup vs baseline: 1.4175x; 1.4175x over previous
#include <cuda_runtime.h>
#include <cstdint>

// SimpleSparseConvNet: rulebook sparse conv, Cin=1, Cout=16.
// out[o, 0:16] += feats[i] * W[k, 0:16] for rulebook pairs (i, o, k).
//
// Degree-aware scatter: every output has deg>=1. deg==1 rows (majority) are
// written with plain STG.128 (no memset, no atomic, no RMW). Only deg>=2
// rows are zeroed and accumulated with red.global.add.v4.f32.

#define MAX_NOUT (4 * 1024 * 1024)

__device__ unsigned int g_counts[MAX_NOUT];

__device__ __forceinline__ void red_add_v4(float* addr, float a, float b, float c, float d) {
    asm volatile("red.global.add.v4.f32 [%0], {%1, %2, %3, %4};"
                 :: "l"(addr), "f"(a), "f"(b), "f"(c), "f"(d)
                 : "memory");
}

// ---- K0: zero counts (L2-resident 7.8MB) -----------------------------------
__global__ void __launch_bounds__(256)
k_zero_counts(int n4) {
    int i = blockIdx.x * blockDim.x + threadIdx.x;
    if (i < n4) reinterpret_cast<uint4*>(g_counts)[i] = make_uint4(0, 0, 0, 0);
}

// ---- K1: histogram of out_idx ----------------------------------------------
__global__ void __launch_bounds__(256)
k_count(const int* __restrict__ out_idx, int M) {
    int m = blockIdx.x * blockDim.x + threadIdx.x;
    if (m < M) atomicAdd(&g_counts[out_idx[m]], 1u);
}

// ---- K2: zero output rows with deg >= 2 -------------------------------------
__global__ void __launch_bounds__(256)
k_zero_multi(float* __restrict__ out, int n_out) {
    int base = (blockIdx.x * blockDim.x + threadIdx.x) * 4;
    if (base >= n_out) return;
    // vectorized counts read (4 outputs per thread)
    uint4 c = reinterpret_cast<const uint4*>(g_counts)[base >> 2];
    const float4 z = make_float4(0.f, 0.f, 0.f, 0.f);
    unsigned int cs[4] = {c.x, c.y, c.z, c.w};
#pragma unroll
    for (int q = 0; q < 4; q++) {
        int o = base + q;
        if (o < n_out && cs[q] >= 2u) {
            float4* op = reinterpret_cast<float4*>(out) + (size_t)o * 4;
            op[0] = z; op[1] = z; op[2] = z; op[3] = z;
        }
    }
}

// ---- K3: degree-aware scatter ------------------------------------------------
__global__ void __launch_bounds__(256)
k_scatter(const float* __restrict__ feats,
          const float* __restrict__ weight,
          const int* __restrict__ in_idx,
          const int* __restrict__ out_idx,
          const int* __restrict__ k_idx,
          float* __restrict__ out,
          int M) {
    int m = blockIdx.x * blockDim.x + threadIdx.x;
    if (m >= M) return;

    const int o = __ldg(&out_idx[m]);
    const int k = __ldg(&k_idx[m]);
    const float f = __ldg(&feats[__ldg(&in_idx[m])]);
    const unsigned int deg = g_counts[o];

    const float4* wp = reinterpret_cast<const float4*>(weight) + (size_t)k * 4;
    float* op = out + (size_t)o * 16;

    if (deg == 1u) {
        // exclusive owner: plain vector stores, no RMW
#pragma unroll
        for (int j = 0; j < 4; j++) {
            float4 w = __ldg(&wp[j]);
            float4 v = make_float4(f * w.x, f * w.y, f * w.z, f * w.w);
            reinterpret_cast<float4*>(op)[j] = v;
        }
    } else {
#pragma unroll
        for (int j = 0; j < 4; j++) {
            float4 w = __ldg(&wp[j]);
            red_add_v4(op + j * 4, f * w.x, f * w.y, f * w.z, f * w.w);
        }
    }
}

extern "C" void kernel_launch(void* const* d_in, const int* in_sizes, int n_in,
                              void* d_out, int out_size) {
    const float* feats  = (const float*)d_in[0];
    const float* weight = (const float*)d_in[1];
    const int* in_idx   = (const int*)d_in[2];
    const int* out_idx  = (const int*)d_in[3];
    const int* k_idx    = (const int*)d_in[4];
    float* out = (float*)d_out;

    const int M = in_sizes[2];
    const int n_out = out_size / 16;

    const int T = 256;
    const int n4 = (n_out + 3) / 4;   // uint4 count of the counts array we touch

    k_zero_counts<<<(n4 + T - 1) / T, T>>>(n4);
    k_count<<<(M + T - 1) / T, T>>>(out_idx, M);
    k_zero_multi<<<((n_out + 3) / 4 + T - 1) / T, T>>>(out, n_out);
    k_scatter<<<(M + T - 1) / T, T>>>(feats, weight, in_idx, out_idx, k_idx, out, M);
}